// round 15
// baseline (speedup 1.0000x reference)
#include <cuda_runtime.h>
#include <math.h>
#include <stdint.h>

#define BB  8
#define NN  325
#define FIN 32
#define TT  24
#define HH  4
#define CC  32
#define HC  128
#define KMAX 8
#define NPAIR 163   // ceil(NN/2)

// -------- scratch (device globals; no allocation allowed) --------
__device__ float  g_Wh  [(size_t)BB * TT * NN * HC];   // [bt][n][o]  ~32MB
__device__ float  g_f1  [(size_t)BB * TT * NN * HH];   // [bt][n][h]
__device__ float  g_f2  [(size_t)BB * TT * NN * HH];
__device__ float  g_Sall[(size_t)BB * TT * HC];        // [bt][o]
__device__ float  g_u1  [HC];                          // [h][f] folded attn vecs
__device__ float  g_u2  [HC];
__device__ float  g_beta[8];                           // [sel][h]
__device__ int    g_nidx[NN * KMAX];
__device__ float  g_nw  [NN * KMAX];
__device__ int    g_ncnt[NN];

// -------- packed f32x2 helpers (Blackwell FFMA2 via PTX only) --------
__device__ __forceinline__ uint64_t pack2(float v) {
    uint64_t r; unsigned u = __float_as_uint(v);
    asm("mov.b64 %0, {%1, %1};" : "=l"(r) : "r"(u));
    return r;
}
__device__ __forceinline__ void fma2(uint64_t& d, uint64_t a, uint64_t b) {
    asm("fma.rn.f32x2 %0, %1, %2, %0;" : "+l"(d) : "l"(a), "l"(b));
}
__device__ __forceinline__ void unpack2(uint64_t v, float& lo, float& hi) {
    unsigned a, b;
    asm("mov.b64 {%0, %1}, %2;" : "=r"(a), "=r"(b) : "l"(v));
    lo = __uint_as_float(a); hi = __uint_as_float(b);
}

// ================= K0: constrain weights + neighbor compaction =================
__global__ void k0_neighbors(const float* __restrict__ iw,
                             const float* __restrict__ base,
                             const float* __restrict__ mask) {
    int i    = blockIdx.x;
    int lane = threadIdx.x;
    __shared__ int   s_idx[KMAX];
    __shared__ float s_val[KMAX];
    if (lane < KMAX) { s_idx[lane] = 0; s_val[lane] = 0.f; }
    __syncwarp();

    float s   = 0.f;
    int   cnt = 0;
    for (int jb = 0; jb < NN; jb += 32) {
        int j = jb + lane;
        float m = 0.f, mv = 0.f;
        if (j < NN) {
            m = mask[i * NN + j];
            float w  = iw  [i * NN + j];
            float bb = base[i * NN + j];
            float v = fminf(fmaxf(w, 0.5f * bb), 1.5f * bb);
            v = fmaxf(v, 0.f);
            mv = v * m;
        }
        s += mv;
        unsigned bal = __ballot_sync(0xffffffffu, m != 0.f);
        if (m != 0.f) {
            int pos = cnt + __popc(bal & ((1u << lane) - 1u));
            if (pos < KMAX) { s_idx[pos] = j; s_val[pos] = mv; }
        }
        cnt += __popc(bal);
    }
    #pragma unroll
    for (int off = 16; off; off >>= 1) s += __shfl_xor_sync(0xffffffffu, s, off);
    if (s == 0.f) s = 1e-6f;
    __syncwarp();

    cnt = min(cnt, KMAX);
    if (lane == 0) g_ncnt[i] = cnt;
    if (lane < KMAX) {
        g_nidx[i * KMAX + lane] = (lane < cnt) ? s_idx[lane] : 0;
        g_nw  [i * KMAX + lane] = (lane < cnt) ? s_val[lane] / s : 0.f;
    }
}

// ================= K0b: one-time fold of attn through W (constants) =========
// u1[h][f] = sum_c Ww[h*C+c][f] * a1[h][c];  beta[sel][h] = sum_c Wb[h*C+c]*a[sel][h][c]
__global__ void k0b_prep(const float* __restrict__ Ww,
                         const float* __restrict__ Wb,
                         const float* __restrict__ attn) {
    int o = threadIdx.x;           // 0..127
    int hh = o >> 5, f = o & 31;
    const float* arow = attn + hh * (2 * CC);
    float s1 = 0.f, s2 = 0.f;
    #pragma unroll
    for (int cc = 0; cc < CC; cc++) {
        float wv = Ww[(hh * 32 + cc) * FIN + f];
        s1 = fmaf(wv, arow[cc],      s1);
        s2 = fmaf(wv, arow[CC + cc], s2);
    }
    g_u1[o] = s1; g_u2[o] = s2;
    if (o < 8) {
        int sel = o >> 2, h2 = o & 3;
        float bsum = 0.f;
        #pragma unroll
        for (int cc = 0; cc < CC; cc++)
            bsum = fmaf(Wb[h2 * 32 + cc], attn[h2 * (2 * CC) + sel * CC + cc], bsum);
        g_beta[o] = bsum;
    }
}

// ================= K1: Wh = xp @ W^T + b (FFMA2); f1/f2 from folded u ========
// 256 threads = 2 n per block. W rows loaded straight from global (L2-hot).
__global__ void __launch_bounds__(256) k1_wh(const float* __restrict__ x,
                                             const float* __restrict__ Ww,
                                             const float* __restrict__ Wb) {
    int blk  = blockIdx.x;
    int b    = blk / NPAIR, np = blk % NPAIR;
    int half = threadIdx.x >> 7;
    int o    = threadIdx.x & 127;
    int n    = np * 2 + half;
    bool valid = (n < NN);

    __shared__ __align__(16) float x_sm[2][FIN * TT];  // [half][f][t]
    __shared__ float u_sm[2][HC];
    __shared__ float beta_sm[8];

    if (valid) {
        const float4* xb = (const float4*)(x + ((size_t)b * NN + n) * (FIN * TT));
        float4* xs = (float4*)x_sm[half];
        #pragma unroll
        for (int idx = o; idx < 192; idx += 128) xs[idx] = xb[idx];
    }
    if (threadIdx.x < 128) {
        u_sm[0][threadIdx.x] = g_u1[threadIdx.x];
        u_sm[1][threadIdx.x] = g_u2[threadIdx.x];
        if (threadIdx.x < 8) beta_sm[threadIdx.x] = g_beta[threadIdx.x];
    }

    // W row for this thread's o, direct from global (LDG.128)
    float wreg[FIN];
    {
        const float4* wrow = (const float4*)(Ww + o * FIN);
        #pragma unroll
        for (int r = 0; r < 8; r++) {
            float4 v = __ldg(&wrow[r]);
            wreg[4*r+0] = v.x; wreg[4*r+1] = v.y; wreg[4*r+2] = v.z; wreg[4*r+3] = v.w;
        }
    }
    uint64_t bias2 = pack2(__ldg(&Wb[o]));
    __syncthreads();

    // ---- main GEMM: 12 packed f32x2 accumulators over t ----
    uint64_t acc2[12];
    #pragma unroll
    for (int q = 0; q < 12; q++) acc2[q] = bias2;

    #pragma unroll
    for (int f = 0; f < FIN; f++) {
        uint64_t wv2 = pack2(wreg[f]);
        const ulonglong2* xr = (const ulonglong2*)&x_sm[half][f * TT];
        #pragma unroll
        for (int q = 0; q < 6; q++) {
            ulonglong2 v = xr[q];
            fma2(acc2[2 * q],     v.x, wv2);
            fma2(acc2[2 * q + 1], v.y, wv2);
        }
    }

    if (valid) {
        #pragma unroll
        for (int q = 0; q < 12; q++) {
            float lo, hi;
            unpack2(acc2[q], lo, hi);
            size_t base0 = ((size_t)(b * TT + 2 * q) * NN + n) * HC + o;
            g_Wh[base0] = lo;
            g_Wh[base0 + (size_t)NN * HC] = hi;
        }
        // f1/f2: (sel in {0,1}) x (h 0..3) x (t 0..23) per n
        #pragma unroll
        for (int idx = o; idx < 192; idx += 128) {
            int sel = idx / 96;
            int rem = idx - sel * 96;
            int tt2 = rem % 24;
            int hh  = rem / 24;
            const float* u = &u_sm[sel][hh * 32];
            float v = beta_sm[sel * 4 + hh];
            #pragma unroll
            for (int f = 0; f < FIN; f++) v = fmaf(x_sm[half][f * TT + tt2], u[f], v);
            size_t fb = ((size_t)(b * TT + tt2) * NN + n) * HH + hh;
            if (sel) g_f2[fb] = v; else g_f1[fb] = v;
        }
    }
}

// ================= K2: S_all[bt][o] = sum_n Wh[bt][n][o], LDG.128 ============
__global__ void __launch_bounds__(512) k2_colsum() {
    int bt = blockIdx.x;
    int l  = threadIdx.x & 31;       // float4 lane over o
    int q  = threadIdx.x >> 5;       // 0..15 n-slice
    __shared__ float4 red[16][32];

    int n0 = q * 21;
    int n1 = min(NN, n0 + 21);
    const float4* base = (const float4*)(g_Wh + (size_t)bt * NN * HC) + l;
    float4 a = make_float4(0.f, 0.f, 0.f, 0.f);
    for (int n = n0; n < n1; n++) {
        float4 v = base[(size_t)n * 32];
        a.x += v.x; a.y += v.y; a.z += v.z; a.w += v.w;
    }
    red[q][l] = a;
    __syncthreads();
    if (threadIdx.x < 32) {
        float4 s = red[0][l];
        #pragma unroll
        for (int k = 1; k < 16; k++) {
            float4 v = red[k][l];
            s.x += v.x; s.y += v.y; s.z += v.z; s.w += v.w;
        }
        ((float4*)(g_Sall + (size_t)bt * HC))[l] = s;
    }
}

// ================= K3: coef once per (t,h) in smem + gather-FMA + transpose ==
// Block = (b,i), 768 threads = 24 warps (warp = t). Threads 0..95 compute the
// 96 coefficient quads into smem while all warps' gathers are in flight.
__global__ void __launch_bounds__(768) k3_out(float* __restrict__ out) {
    int blk = blockIdx.x;
    int b = blk / NN, i = blk % NN;
    __shared__ float sm[TT * HC];            // [t][o]
    __shared__ __align__(16) float coef_sm[TT * HH * 4];   // [t][h]{a0,c0,c1,c2}

    int tid = threadIdx.x;
    int t = tid >> 5;                  // 0..23
    int l = tid & 31;
    int h = l >> 3;
    int bt = b * TT + t;

    int j0 = g_nidx[i * KMAX + 0];
    int j1 = g_nidx[i * KMAX + 1];
    int j2 = g_nidx[i * KMAX + 2];
    int cnt = min(g_ncnt[i], 3);

    // bulk gathers first — L2 latency overlaps the coef phase below
    const float4* wh = (const float4*)(g_Wh + (size_t)bt * NN * HC);
    float4 s  = ((const float4*)(g_Sall + (size_t)bt * HC))[l];
    float4 w0 = wh[(size_t)j0 * 32 + l];
    float4 w1 = wh[(size_t)j1 * 32 + l];
    float4 w2 = wh[(size_t)j2 * 32 + l];

    // threads 0..95: one (tc, hc) quad each
    if (tid < 96) {
        int tc = tid >> 2, hc = tid & 3;
        int btc = b * TT + tc;
        float nw0 = g_nw[i * KMAX + 0];
        float nw1 = g_nw[i * KMAX + 1];
        float nw2 = g_nw[i * KMAX + 2];
        const float* f2b = g_f2 + (size_t)btc * NN * HH;
        float f1i = g_f1[((size_t)btc * NN + i) * HH + hc];
        float m = 0.f, s0 = 0.f, s1 = 0.f, s2 = 0.f;
        if (0 < cnt) {
            float e = f1i + f2b[j0 * HH + hc];
            s0 = ((e > 0.f) ? e : 0.2f * e) + nw0; m = fmaxf(m, s0);
        }
        if (1 < cnt) {
            float e = f1i + f2b[j1 * HH + hc];
            s1 = ((e > 0.f) ? e : 0.2f * e) + nw1; m = fmaxf(m, s1);
        }
        if (2 < cnt) {
            float e = f1i + f2b[j2 * HH + hc];
            s2 = ((e > 0.f) ? e : 0.2f * e) + nw2; m = fmaxf(m, s2);
        }
        float E0  = __expf(-m);
        float Ek0 = (0 < cnt) ? __expf(s0 - m) : 0.f;
        float Ek1 = (1 < cnt) ? __expf(s1 - m) : 0.f;
        float Ek2 = (2 < cnt) ? __expf(s2 - m) : 0.f;
        float denom = (float)(NN - cnt) * E0 + Ek0 + Ek1 + Ek2;
        float rd = 1.f / denom;
        float4 cf;
        cf.x = E0 * rd;
        cf.y = (0 < cnt) ? (Ek0 - E0) * rd : 0.f;
        cf.z = (1 < cnt) ? (Ek1 - E0) * rd : 0.f;
        cf.w = (2 < cnt) ? (Ek2 - E0) * rd : 0.f;
        ((float4*)coef_sm)[tid] = cf;
    }
    __syncthreads();

    float4 cf = ((const float4*)coef_sm)[t * 4 + h];

    float4 acc;
    acc.x = fmaf(cf.x, s.x, fmaf(cf.y, w0.x, fmaf(cf.z, w1.x, cf.w * w2.x)));
    acc.y = fmaf(cf.x, s.y, fmaf(cf.y, w0.y, fmaf(cf.z, w1.y, cf.w * w2.y)));
    acc.z = fmaf(cf.x, s.z, fmaf(cf.y, w0.z, fmaf(cf.z, w1.z, cf.w * w2.z)));
    acc.w = fmaf(cf.x, s.w, fmaf(cf.y, w0.w, fmaf(cf.z, w1.w, cf.w * w2.w)));
    ((float4*)&sm[t * HC])[l] = acc;
    __syncthreads();

    // transpose write: out[b][i][o][t], float4 along t
    int g = tid >> 7;                  // 0..5
    int o = tid & 127;
    float4 v;
    v.x = sm[(4 * g + 0) * HC + o];
    v.y = sm[(4 * g + 1) * HC + o];
    v.z = sm[(4 * g + 2) * HC + o];
    v.w = sm[(4 * g + 3) * HC + o];
    float* ob = out + ((size_t)(b * NN + i) * HC + o) * TT;
    ((float4*)ob)[g] = v;
}

// ================= launch =================
extern "C" void kernel_launch(void* const* d_in, const int* in_sizes, int n_in,
                              void* d_out, int out_size) {
    const float* x    = (const float*)d_in[0];  // (B, N, F_IN, T)
    const float* Ww   = (const float*)d_in[1];  // (HC, F_IN)
    const float* Wb   = (const float*)d_in[2];  // (HC,)
    const float* attn = (const float*)d_in[3];  // (H, 2C)
    const float* iw   = (const float*)d_in[4];  // (N, N)
    const float* base = (const float*)d_in[5];  // (N, N)
    const float* mask = (const float*)d_in[6];  // (N, N)
    float* out = (float*)d_out;                 // (B, N, HC, T)
    (void)in_sizes; (void)n_in; (void)out_size;

    k0_neighbors<<<NN, 32>>>(iw, base, mask);
    k0b_prep<<<1, HC>>>(Ww, Wb, attn);
    k1_wh<<<BB * NPAIR, 256>>>(x, Ww, Wb);
    k2_colsum<<<BB * TT, 512>>>();
    k3_out<<<BB * NN, 768>>>(out);
}